// round 11
// baseline (speedup 1.0000x reference)
// Round 11: recurrence sync rebuilt on mbarrier + st.async producer/consumer pipeline
// (replaces whole-cluster barrier whose release-drain exposed the DSMEM pushes);
// MUFU transcendentals in the pointwise update. Matvec/gates/conv/gnorm = r10.
#include <cuda_runtime.h>
#include <math.h>
#include <stdint.h>

#define BB 4
#define SS 2048
#define DD 1024
#define NH 4
#define DH 256
#define KK 4
#define NSLICE 8

typedef unsigned long long u64;

// ---------------- scratch (static device arrays; no allocation) ----------------
__device__ float g_xconv[BB * SS * DD];            // 33.5M floats
__device__ float g_gates[SS * NH * 4 * BB * DH];   // [t][h][g][b][e]
__device__ float g_yout [BB * SS * NH * DH];       // [b][t][h][e]

// ---------------- helpers ----------------
__device__ __forceinline__ u64 pk2(float a, float b) {
    u64 r; asm("mov.b64 %0,{%1,%2};" : "=l"(r) : "f"(a), "f"(b)); return r;
}
__device__ __forceinline__ u64 f2fma(u64 a, u64 b, u64 c) {
    u64 d; asm("fma.rn.f32x2 %0,%1,%2,%3;" : "=l"(d) : "l"(a), "l"(b), "l"(c)); return d;
}
__device__ __forceinline__ float f2lo(u64 v) { return __uint_as_float((unsigned)v); }
__device__ __forceinline__ float f2hi(u64 v) { return __uint_as_float((unsigned)(v >> 32)); }
__device__ __forceinline__ uint32_t smem_u32(const void* p) {
    uint32_t a;
    asm("{ .reg .u64 t; cvta.to.shared.u64 t, %1; cvt.u32.u64 %0, t; }" : "=r"(a) : "l"(p));
    return a;
}
__device__ __forceinline__ uint32_t mapa_u32(uint32_t local, int rank) {
    uint32_t r;
    asm("mapa.shared::cluster.u32 %0, %1, %2;" : "=r"(r) : "r"(local), "r"(rank));
    return r;
}
__device__ __forceinline__ void mbar_init(uint32_t a, unsigned cnt) {
    asm volatile("mbarrier.init.shared.b64 [%0], %1;" :: "r"(a), "r"(cnt) : "memory");
}
__device__ __forceinline__ void mbar_arrive_expect_tx(uint32_t a, unsigned tx) {
    asm volatile("mbarrier.arrive.expect_tx.shared.b64 _, [%0], %1;" :: "r"(a), "r"(tx) : "memory");
}
__device__ __forceinline__ void mbar_arrive_remote(uint32_t raddr) {
    asm volatile("mbarrier.arrive.release.cluster.shared::cluster.b64 _, [%0];"
                 :: "r"(raddr) : "memory");
}
__device__ __forceinline__ void mbar_wait(uint32_t a, unsigned parity) {
    unsigned done;
    asm volatile(
        "{\n\t.reg .pred p;\n\t"
        "mbarrier.try_wait.parity.acquire.cluster.shared::cta.b64 p, [%1], %2;\n\t"
        "selp.b32 %0, 1, 0, p;\n\t}"
        : "=r"(done) : "r"(a), "r"(parity) : "memory");
    while (!done) {
        asm volatile(
            "{\n\t.reg .pred p;\n\t"
            "mbarrier.try_wait.parity.acquire.cluster.shared::cta.b64 p, [%1], %2, 0x989680;\n\t"
            "selp.b32 %0, 1, 0, p;\n\t}"
            : "=r"(done) : "r"(a), "r"(parity) : "memory");
    }
}
__device__ __forceinline__ void st_async_f32(uint32_t raddr, uint32_t rmbar, float v) {
    asm volatile(
        "st.async.weak.shared::cluster.mbarrier::complete_tx::bytes.b32 [%0], %1, [%2];"
        :: "r"(raddr), "r"(__float_as_uint(v)), "r"(rmbar) : "memory");
}
#define CLUSTER_SYNC() do { \
    asm volatile("barrier.cluster.arrive.aligned;" ::: "memory"); \
    asm volatile("barrier.cluster.wait.aligned;" ::: "memory"); } while (0)

// ---------------- causal depthwise conv (K=4) + swish ----------------
__global__ void conv_swish_k(const float* __restrict__ x,
                             const float* __restrict__ ck,
                             const float* __restrict__ cb) {
    int bs = blockIdx.x;
    int b = bs >> 11, s = bs & (SS - 1);
    int q = threadIdx.x;  // d-quad 0..255
    const float4* x4 = (const float4*)x;
    const float4* k4 = (const float4*)ck;
    float4 k0 = k4[0 * (DD / 4) + q];
    float4 k1 = k4[1 * (DD / 4) + q];
    float4 k2 = k4[2 * (DD / 4) + q];
    float4 k3 = k4[3 * (DD / 4) + q];
    float4 acc = ((const float4*)cb)[q];
    int rowq = (b * SS + s) * (DD / 4);
#define CONV_TAP(kk, kv)                                            \
    { int sr = s - 3 + (kk);                                        \
      if (sr >= 0) {                                                \
          float4 xv = x4[(b * SS + sr) * (DD / 4) + q];             \
          acc.x += (kv).x * xv.x; acc.y += (kv).y * xv.y;           \
          acc.z += (kv).z * xv.z; acc.w += (kv).w * xv.w; } }
    CONV_TAP(0, k0) CONV_TAP(1, k1) CONV_TAP(2, k2) CONV_TAP(3, k3)
#undef CONV_TAP
    float4 r;
    r.x = acc.x / (1.f + expf(-acc.x));
    r.y = acc.y / (1.f + expf(-acc.y));
    r.z = acc.z / (1.f + expf(-acc.z));
    r.w = acc.w / (1.f + expf(-acc.w));
    ((float4*)g_xconv)[rowq + q] = r;
}

// ---------------- gate GEMMs: gates[t][h][g][b][e]  (packed f32x2 FMA) ----------------
__global__ void __launch_bounds__(256, 1)
gates_gemm_k(const float* __restrict__ x,
             const float* __restrict__ w_i, const float* __restrict__ w_f,
             const float* __restrict__ w_z, const float* __restrict__ w_o) {
    int h = blockIdx.z >> 2, g = blockIdx.z & 3;
    int b = blockIdx.y >> 1, eh = blockIdx.y & 1;
    int sch = blockIdx.x;
    const float* in = (g < 2) ? g_xconv : x;
    const float* W = (g == 0) ? w_i : (g == 1) ? w_f : (g == 2) ? w_z : w_o;

    int tid = threadIdx.x, lane = tid & 31, wid = tid >> 5;
    int el = wid * 16 + (lane & 15);
    int dh = lane >> 4;
    int eg = eh * 128 + el;
    int dbase = dh * 128;

    ulonglong2 wq[32];
#pragma unroll
    for (int j = 0; j < 32; j++) {
        const float* p = W + (size_t)(h * DH + dbase + 4 * j) * DH + eg;
        wq[j].x = pk2(p[0], p[DH]);
        wq[j].y = pk2(p[2 * DH], p[3 * DH]);
    }

    __shared__ __align__(16) float As[32][256];

    for (int tt = 0; tt < 4; tt++) {
        int s0 = (sch * 4 + tt) * 32;
        for (int l = tid; l < 32 * 64; l += 256) {
            int r = l >> 6, q = l & 63;
            ((float4*)As[r])[q] =
                ((const float4*)(in + (size_t)(b * SS + s0 + r) * DD + h * DH))[q];
        }
        __syncthreads();
#pragma unroll 1
        for (int r = 0; r < 32; r++) {
            u64 al = 0, ah = 0;
#pragma unroll
            for (int j = 0; j < 32; j++) {
                ulonglong2 av = *(const ulonglong2*)&As[r][dbase + 4 * j];
                al = f2fma(wq[j].x, av.x, al);
                ah = f2fma(wq[j].y, av.y, ah);
            }
            float sum = (f2lo(al) + f2hi(al)) + (f2lo(ah) + f2hi(ah));
            sum += __shfl_xor_sync(0xffffffffu, sum, 16);
            if (dh == 0)
                g_gates[(size_t)(((s0 + r) * NH + h) * 4 + g) * (BB * DH) + b * DH + eg] = sum;
        }
        __syncthreads();
    }
}

// ---------------- recurrence: 8-CTA clusters, mbarrier/st.async pipeline ----------------
__global__ void __launch_bounds__(256, 1) __cluster_dims__(NSLICE, 1, 1)
rec_k(const float* __restrict__ Wr, const float* __restrict__ rb) {
    int h = blockIdx.y, si = blockIdx.x;
    int tid = threadIdx.x, lane = tid & 31, wid = tid >> 5;
    int g = wid & 3, ehi = wid >> 2;
    int dh = lane >> 4;
    int e = ehi * 16 + (lane & 15);
    int eg = si * 32 + e;
    int dbase = dh * 128;

    ulonglong2 wq[32];
#pragma unroll
    for (int j = 0; j < 32; j++) {
        const float* p = Wr + (size_t)((h * DH + dbase + 4 * j) * 4 + g) * DH + eg;
        wq[j].x = pk2(p[0], p[4 * DH]);
        wq[j].y = pk2(p[8 * DH], p[12 * DH]);
    }

    int sb = tid >> 5;
    int se = tid & 31;
    int seg = si * 32 + se;
    float bI = 0, bF = 0, bZ = 0, bO = 0, c = 0, n = 0, m = 0;
    if (tid < 128) {
        bI = rb[(0 * NH + h) * DH + seg];
        bF = rb[(1 * NH + h) * DH + seg];
        bZ = rb[(2 * NH + h) * DH + seg];
        bO = rb[(3 * NH + h) * DH + seg];
    }

    // y_s[buf][b][e], contiguous buffers (buf stride = BB*DH*4 = 4096 bytes)
    __shared__ __align__(16) float y_s[2][BB][DH];
    __shared__ float raw_s[4][BB][32];
    // mb[0..1] = full[buf] (1 arrive + 4096 tx), mb[2..3] = empty[buf] (8 arrives)
    __shared__ __align__(8) unsigned long long mb[4];

    uint32_t mb0 = smem_u32(&mb[0]);
    if (tid == 0) {
        mbar_init(mb0 + 0, 1);
        mbar_init(mb0 + 8, 1);
        mbar_init(mb0 + 16, NSLICE);
        mbar_init(mb0 + 24, NSLICE);
        // pre-arm both full barriers for their first fill
        mbar_arrive_expect_tx(mb0 + 0, BB * DH * 4);
        mbar_arrive_expect_tx(mb0 + 8, BB * DH * 4);
    }
    for (int i = tid; i < BB * DH / 4; i += 256)
        ((float4*)&y_s[0][0][0])[i] = make_float4(0.f, 0.f, 0.f, 0.f);
    __syncthreads();
    CLUSTER_SYNC();  // all CTAs: mbarriers init+armed, buf0 zeroed

    // per-rank remote base addresses (mapa is offset-preserving)
    uint32_t dstBase[NSLICE], mbarBase[NSLICE];
    uint32_t myY0 = smem_u32(&y_s[0][sb][seg]);  // valid for tid<128
#pragma unroll
    for (int r = 0; r < NSLICE; r++) {
        dstBase[r] = mapa_u32(myY0, r);     // + 4096*buf selects buffer
        mbarBase[r] = mapa_u32(mb0, r);     // + 8*buf = full[buf]; +16+8*buf = empty[buf]
    }

    unsigned phF0 = 0, phF1 = 0, phE0 = 0, phE1 = 0;

    for (int t = 0; t < SS; t++) {
        int B = t & 1;

        // prefetch gate inputs (L2 loads issue before the wait)
        float gI = 0, gF = 0, gZ = 0, gO = 0;
        if (tid < 128) {
            const float* gp = g_gates + (size_t)(t * NH + h) * 4 * (BB * DH) + sb * DH + seg;
            gI = gp[0];
            gF = gp[BB * DH];
            gZ = gp[2 * BB * DH];
            gO = gp[3 * BB * DH];
        }
        if (t > 0) {
            // wait for all 8 CTAs' st.async pushes into y_s[B]
            unsigned ph = B ? phF1 : phF0;
            mbar_wait(mb0 + 8 * B, ph);
            if (B) phF1 ^= 1; else phF0 ^= 1;
            if (tid == 0) mbar_arrive_expect_tx(mb0 + 8 * B, BB * DH * 4);  // re-arm next phase
        }

        // 4-batch matvec over this thread's 128-d half, packed f32x2
        u64 a0l = 0, a0h = 0, a1l = 0, a1h = 0, a2l = 0, a2h = 0, a3l = 0, a3h = 0;
#pragma unroll
        for (int j = 0; j < 32; j++) {
            ulonglong2 wv = wq[j];
            ulonglong2 y0 = *(const ulonglong2*)&y_s[B][0][dbase + 4 * j];
            a0l = f2fma(wv.x, y0.x, a0l); a0h = f2fma(wv.y, y0.y, a0h);
            ulonglong2 y1 = *(const ulonglong2*)&y_s[B][1][dbase + 4 * j];
            a1l = f2fma(wv.x, y1.x, a1l); a1h = f2fma(wv.y, y1.y, a1h);
            ulonglong2 y2 = *(const ulonglong2*)&y_s[B][2][dbase + 4 * j];
            a2l = f2fma(wv.x, y2.x, a2l); a2h = f2fma(wv.y, y2.y, a2h);
            ulonglong2 y3 = *(const ulonglong2*)&y_s[B][3][dbase + 4 * j];
            a3l = f2fma(wv.x, y3.x, a3l); a3h = f2fma(wv.y, y3.y, a3h);
        }
        float r0 = (f2lo(a0l) + f2hi(a0l)) + (f2lo(a0h) + f2hi(a0h));
        float r1 = (f2lo(a1l) + f2hi(a1l)) + (f2lo(a1h) + f2hi(a1h));
        float r2 = (f2lo(a2l) + f2hi(a2l)) + (f2lo(a2h) + f2hi(a2h));
        float r3 = (f2lo(a3l) + f2hi(a3l)) + (f2lo(a3h) + f2hi(a3h));
        r0 += __shfl_xor_sync(0xffffffffu, r0, 16);
        r1 += __shfl_xor_sync(0xffffffffu, r1, 16);
        r2 += __shfl_xor_sync(0xffffffffu, r2, 16);
        r3 += __shfl_xor_sync(0xffffffffu, r3, 16);
        if (dh == 0) {
            raw_s[g][0][e] = r0;
            raw_s[g][1][e] = r1;
            raw_s[g][2][e] = r2;
            raw_s[g][3][e] = r3;
        }
        __syncthreads();  // raw exchange; also: all warps done reading y_s[B]

        // broadcast "my CTA finished reading y_s[B]" to every rank's empty[B]
        if (tid == 0) {
#pragma unroll
            for (int r = 0; r < NSLICE; r++)
                mbar_arrive_remote(mbarBase[r] + 16 + 8 * B);
        }

        if (tid < 128) {
            float rI = raw_s[0][sb][se] + gI + bI;
            float rF = raw_s[1][sb][se] + gF + bF;
            float rZ = raw_s[2][sb][se] + gZ + bZ;
            float rO = raw_s[3][sb][se] + gO + bO;
            // MUFU-based stabilized update (overflow-safe at +/- inf)
            float lsf = fminf(rF, 0.f) - __logf(1.f + __expf(-fabsf(rF)));
            float lfm = m + lsf;
            float mn = fmaxf(rI, lfm);
            float ig = __expf(rI - mn);
            float fg = __expf(lfm - mn);
            float tz = 1.f - 2.f / (1.f + __expf(2.f * rZ));  // tanh(rZ)
            c = fg * c + ig * tz;
            n = fg * n + ig;
            m = mn;
            float yv = (c / n) / (1.f + __expf(-rO));

            int Bn = B ^ 1;
            if (t > 0) {
                // all ranks must be done reading y_s[Bn] (their step t-1 matvec)
                unsigned ph = Bn ? phE1 : phE0;
                mbar_wait(mb0 + 16 + 8 * Bn, ph);
                if (Bn) phE1 ^= 1; else phE0 ^= 1;
            }
            // push my y element into y_s[Bn] of every rank, tx onto their full[Bn]
#pragma unroll
            for (int r = 0; r < NSLICE; r++)
                st_async_f32(dstBase[r] + 4096 * Bn, mbarBase[r] + 8 * Bn, yv);
            g_yout[(size_t)((sb * SS + t) * NH + h) * DH + seg] = yv;
        }
    }
    // drain: final step's stores (t=2047, B=1) target full[0]; collect before exit
    mbar_wait(mb0 + 0, phF0);
    CLUSTER_SYNC();
}

// ---------------- per-head GroupNorm + affine ----------------
__global__ void gnorm_k(const float* __restrict__ gsc,
                        const float* __restrict__ gbi,
                        float* __restrict__ out) {
    int bs = blockIdx.x;
    int b = bs >> 11, s = bs & (SS - 1);
    int lane = threadIdx.x & 31, h = threadIdx.x >> 5;
    const float* yp = g_yout + (size_t)((b * SS + s) * NH + h) * DH;
    float4 v0 = ((const float4*)yp)[lane * 2];
    float4 v1 = ((const float4*)yp)[lane * 2 + 1];
    float sum = v0.x + v0.y + v0.z + v0.w + v1.x + v1.y + v1.z + v1.w;
    float sq = v0.x * v0.x + v0.y * v0.y + v0.z * v0.z + v0.w * v0.w +
               v1.x * v1.x + v1.y * v1.y + v1.z * v1.z + v1.w * v1.w;
#pragma unroll
    for (int o = 16; o; o >>= 1) {
        sum += __shfl_xor_sync(0xffffffffu, sum, o);
        sq += __shfl_xor_sync(0xffffffffu, sq, o);
    }
    float mean = sum * (1.f / DH);
    float var = sq * (1.f / DH) - mean * mean;
    float rs = rsqrtf(var + 1e-6f);
    int dbase = h * DH + lane * 8;
    float4 sc0 = ((const float4*)(gsc + dbase))[0];
    float4 sc1 = ((const float4*)(gsc + dbase))[1];
    float4 bi0 = ((const float4*)(gbi + dbase))[0];
    float4 bi1 = ((const float4*)(gbi + dbase))[1];
    float* op = out + (size_t)(b * SS + s) * DD + dbase;
    float4 o0, o1;
    o0.x = (v0.x - mean) * rs * sc0.x + bi0.x;
    o0.y = (v0.y - mean) * rs * sc0.y + bi0.y;
    o0.z = (v0.z - mean) * rs * sc0.z + bi0.z;
    o0.w = (v0.w - mean) * rs * sc0.w + bi0.w;
    o1.x = (v1.x - mean) * rs * sc1.x + bi1.x;
    o1.y = (v1.y - mean) * rs * sc1.y + bi1.y;
    o1.z = (v1.z - mean) * rs * sc1.z + bi1.z;
    o1.w = (v1.w - mean) * rs * sc1.w + bi1.w;
    ((float4*)op)[0] = o0;
    ((float4*)op)[1] = o1;
}

// ---------------- launch ----------------
extern "C" void kernel_launch(void* const* d_in, const int* in_sizes, int n_in,
                              void* d_out, int out_size) {
    const float* x   = (const float*)d_in[0];
    const float* ck  = (const float*)d_in[1];
    const float* cb  = (const float*)d_in[2];
    const float* w_i = (const float*)d_in[3];
    const float* w_f = (const float*)d_in[4];
    const float* w_z = (const float*)d_in[5];
    const float* w_o = (const float*)d_in[6];
    const float* wr  = (const float*)d_in[7];
    const float* rb  = (const float*)d_in[8];
    const float* gsc = (const float*)d_in[9];
    const float* gbi = (const float*)d_in[10];
    float* out = (float*)d_out;

    conv_swish_k<<<BB * SS, 256>>>(x, ck, cb);
    dim3 gg(16, 8, 16);
    gates_gemm_k<<<gg, 256>>>(x, w_i, w_f, w_z, w_o);
    dim3 gr(NSLICE, NH);  // clusters of 8 CTAs along x => one cluster per head
    rec_k<<<gr, 256>>>(wr, rb);
    gnorm_k<<<BB * SS, 128>>>(gsc, gbi, out);
}

// round 12
// speedup vs baseline: 1.5342x; 1.5342x over previous
// Round 12: revert to r10's proven split cluster-barrier sync; keep r11's proven MUFU
// pointwise; NEW: one 8-CTA cluster per (batch, head) => 128 CTAs, 4x matvec parallelism
// (batches are independent in the recurrence; merging them was costing critical-path FMA).
#include <cuda_runtime.h>
#include <math.h>
#include <stdint.h>

#define BB 4
#define SS 2048
#define DD 1024
#define NH 4
#define DH 256
#define KK 4
#define NSLICE 8

typedef unsigned long long u64;

// ---------------- scratch (static device arrays; no allocation) ----------------
__device__ float g_xconv[BB * SS * DD];            // 33.5M floats
__device__ float g_gates[SS * NH * 4 * BB * DH];   // [t][h][g][b][e]
__device__ float g_yout [BB * SS * NH * DH];       // [b][t][h][e]

// ---------------- helpers ----------------
__device__ __forceinline__ u64 pk2(float a, float b) {
    u64 r; asm("mov.b64 %0,{%1,%2};" : "=l"(r) : "f"(a), "f"(b)); return r;
}
__device__ __forceinline__ u64 f2fma(u64 a, u64 b, u64 c) {
    u64 d; asm("fma.rn.f32x2 %0,%1,%2,%3;" : "=l"(d) : "l"(a), "l"(b), "l"(c)); return d;
}
__device__ __forceinline__ float f2lo(u64 v) { return __uint_as_float((unsigned)v); }
__device__ __forceinline__ float f2hi(u64 v) { return __uint_as_float((unsigned)(v >> 32)); }
__device__ __forceinline__ uint32_t smem_u32(const void* p) {
    uint32_t a;
    asm("{ .reg .u64 t; cvta.to.shared.u64 t, %1; cvt.u32.u64 %0, t; }" : "=r"(a) : "l"(p));
    return a;
}
__device__ __forceinline__ void sts_cluster_f32(uint32_t local_addr, int rank, float v) {
    uint32_t ra;
    asm volatile("mapa.shared::cluster.u32 %0, %1, %2;" : "=r"(ra) : "r"(local_addr), "r"(rank));
    asm volatile("st.shared::cluster.f32 [%0], %1;" :: "r"(ra), "f"(v) : "memory");
}
#define CLUSTER_ARRIVE() asm volatile("barrier.cluster.arrive.aligned;" ::: "memory")
#define CLUSTER_WAIT()   asm volatile("barrier.cluster.wait.aligned;" ::: "memory")

// ---------------- causal depthwise conv (K=4) + swish ----------------
__global__ void conv_swish_k(const float* __restrict__ x,
                             const float* __restrict__ ck,
                             const float* __restrict__ cb) {
    int bs = blockIdx.x;
    int b = bs >> 11, s = bs & (SS - 1);
    int q = threadIdx.x;  // d-quad 0..255
    const float4* x4 = (const float4*)x;
    const float4* k4 = (const float4*)ck;
    float4 k0 = k4[0 * (DD / 4) + q];
    float4 k1 = k4[1 * (DD / 4) + q];
    float4 k2 = k4[2 * (DD / 4) + q];
    float4 k3 = k4[3 * (DD / 4) + q];
    float4 acc = ((const float4*)cb)[q];
    int rowq = (b * SS + s) * (DD / 4);
#define CONV_TAP(kk, kv)                                            \
    { int sr = s - 3 + (kk);                                        \
      if (sr >= 0) {                                                \
          float4 xv = x4[(b * SS + sr) * (DD / 4) + q];             \
          acc.x += (kv).x * xv.x; acc.y += (kv).y * xv.y;           \
          acc.z += (kv).z * xv.z; acc.w += (kv).w * xv.w; } }
    CONV_TAP(0, k0) CONV_TAP(1, k1) CONV_TAP(2, k2) CONV_TAP(3, k3)
#undef CONV_TAP
    float4 r;
    r.x = acc.x / (1.f + expf(-acc.x));
    r.y = acc.y / (1.f + expf(-acc.y));
    r.z = acc.z / (1.f + expf(-acc.z));
    r.w = acc.w / (1.f + expf(-acc.w));
    ((float4*)g_xconv)[rowq + q] = r;
}

// ---------------- gate GEMMs: gates[t][h][g][b][e]  (packed f32x2 FMA) ----------------
__global__ void __launch_bounds__(256, 1)
gates_gemm_k(const float* __restrict__ x,
             const float* __restrict__ w_i, const float* __restrict__ w_f,
             const float* __restrict__ w_z, const float* __restrict__ w_o) {
    int h = blockIdx.z >> 2, g = blockIdx.z & 3;
    int b = blockIdx.y >> 1, eh = blockIdx.y & 1;
    int sch = blockIdx.x;
    const float* in = (g < 2) ? g_xconv : x;
    const float* W = (g == 0) ? w_i : (g == 1) ? w_f : (g == 2) ? w_z : w_o;

    int tid = threadIdx.x, lane = tid & 31, wid = tid >> 5;
    int el = wid * 16 + (lane & 15);
    int dh = lane >> 4;
    int eg = eh * 128 + el;
    int dbase = dh * 128;

    ulonglong2 wq[32];
#pragma unroll
    for (int j = 0; j < 32; j++) {
        const float* p = W + (size_t)(h * DH + dbase + 4 * j) * DH + eg;
        wq[j].x = pk2(p[0], p[DH]);
        wq[j].y = pk2(p[2 * DH], p[3 * DH]);
    }

    __shared__ __align__(16) float As[32][256];

    for (int tt = 0; tt < 4; tt++) {
        int s0 = (sch * 4 + tt) * 32;
        for (int l = tid; l < 32 * 64; l += 256) {
            int r = l >> 6, q = l & 63;
            ((float4*)As[r])[q] =
                ((const float4*)(in + (size_t)(b * SS + s0 + r) * DD + h * DH))[q];
        }
        __syncthreads();
#pragma unroll 1
        for (int r = 0; r < 32; r++) {
            u64 al = 0, ah = 0;
#pragma unroll
            for (int j = 0; j < 32; j++) {
                ulonglong2 av = *(const ulonglong2*)&As[r][dbase + 4 * j];
                al = f2fma(wq[j].x, av.x, al);
                ah = f2fma(wq[j].y, av.y, ah);
            }
            float sum = (f2lo(al) + f2hi(al)) + (f2lo(ah) + f2hi(ah));
            sum += __shfl_xor_sync(0xffffffffu, sum, 16);
            if (dh == 0)
                g_gates[(size_t)(((s0 + r) * NH + h) * 4 + g) * (BB * DH) + b * DH + eg] = sum;
        }
        __syncthreads();
    }
}

// ---------------- recurrence: one 8-CTA cluster per (b,h); DSMEM y exchange ----------------
__global__ void __launch_bounds__(256, 1) __cluster_dims__(NSLICE, 1, 1)
rec_k(const float* __restrict__ Wr, const float* __restrict__ rb) {
    int hb = blockIdx.y;            // h*BB + b
    int h = hb >> 2, b = hb & 3;
    int si = blockIdx.x;            // cluster rank = e-slice
    int tid = threadIdx.x, lane = tid & 31, wid = tid >> 5;
    int g = wid & 3, ehi = wid >> 2;
    int dh = lane >> 4;
    int e = ehi * 16 + (lane & 15);     // 0..31 within slice
    int eg = si * 32 + e;
    int dbase = dh * 128;

    // packed recurrent weights: W[h][d][g][eg], pairs; stride 4*DH per d
    ulonglong2 wq[32];
#pragma unroll
    for (int j = 0; j < 32; j++) {
        const float* p = Wr + (size_t)((h * DH + dbase + 4 * j) * 4 + g) * DH + eg;
        wq[j].x = pk2(p[0], p[4 * DH]);
        wq[j].y = pk2(p[8 * DH], p[12 * DH]);
    }

    // state threads: tid<32 -> e within slice
    int se = lane;                  // for tid<32
    int seg = si * 32 + se;
    float bI = 0, bF = 0, bZ = 0, bO = 0, c = 0, n = 0, m = 0;
    if (tid < 32) {
        bI = rb[(0 * NH + h) * DH + seg];
        bF = rb[(1 * NH + h) * DH + seg];
        bZ = rb[(2 * NH + h) * DH + seg];
        bO = rb[(3 * NH + h) * DH + seg];
    }

    // double-buffered full y for THIS batch (256 e), filled by cluster pushes
    __shared__ __align__(16) float y_s[2][DH];
    __shared__ float raw_s[4][32];

    for (int i = tid; i < DH; i += 256) y_s[0][i] = 0.f;
    CLUSTER_ARRIVE();  // paired with the wait at top of t=0

    uint32_t ya0 = 0, ya1 = 0;
    if (tid < 32) {
        ya0 = smem_u32(&y_s[0][seg]);
        ya1 = smem_u32(&y_s[1][seg]);
    }

    const float* gbase = g_gates + (size_t)h * 4 * (BB * DH) + b * DH;
    float* ybase = g_yout + (size_t)(b * SS * NH + h) * DH;

    for (int t = 0; t < SS; t++) {
        int rd = t & 1;

        // prefetch gate inputs (issue before barrier wait)
        float gI = 0, gF = 0, gZ = 0, gO = 0;
        if (tid < 32) {
            const float* gp = gbase + (size_t)t * NH * 4 * (BB * DH) + seg;
            gI = gp[0];
            gF = gp[BB * DH];
            gZ = gp[2 * BB * DH];
            gO = gp[3 * BB * DH];
        }
        CLUSTER_WAIT();  // all pushes into y_s[rd] complete (pairs with prior arrive)

        // 1-batch matvec over this thread's 128-d half, packed f32x2
        u64 al = 0, ah = 0;
#pragma unroll
        for (int j = 0; j < 32; j++) {
            ulonglong2 yv = *(const ulonglong2*)&y_s[rd][dbase + 4 * j];
            al = f2fma(wq[j].x, yv.x, al);
            ah = f2fma(wq[j].y, yv.y, ah);
        }
        float r0 = (f2lo(al) + f2hi(al)) + (f2lo(ah) + f2hi(ah));
        r0 += __shfl_xor_sync(0xffffffffu, r0, 16);
        if (dh == 0) raw_s[g][e] = r0;
        __syncthreads();

        if (tid < 32) {
            float rI = raw_s[0][se] + gI + bI;
            float rF = raw_s[1][se] + gF + bF;
            float rZ = raw_s[2][se] + gZ + bZ;
            float rO = raw_s[3][se] + gO + bO;
            // MUFU stabilized update (precision proven in r11: rel_err 3.7e-7)
            float lsf = fminf(rF, 0.f) - __logf(1.f + __expf(-fabsf(rF)));
            float lfm = m + lsf;
            float mn = fmaxf(rI, lfm);
            float ig = __expf(rI - mn);
            float fg = __expf(lfm - mn);
            float tz = 1.f - 2.f / (1.f + __expf(2.f * rZ));  // tanh(rZ)
            c = fg * c + ig * tz;
            n = fg * n + ig;
            m = mn;
            float yv = (c / n) / (1.f + __expf(-rO));
            uint32_t dst = rd ? ya0 : ya1;
#pragma unroll
            for (int r = 0; r < NSLICE; r++)
                sts_cluster_f32(dst, r, yv);
            ybase[(size_t)t * NH * DH + seg] = yv;
        }
        // release: pushes for step t visible after peers' next wait
        CLUSTER_ARRIVE();
    }
    CLUSTER_WAIT();  // balance final arrive; no early exit under in-flight DSMEM stores
}

// ---------------- per-head GroupNorm + affine ----------------
__global__ void gnorm_k(const float* __restrict__ gsc,
                        const float* __restrict__ gbi,
                        float* __restrict__ out) {
    int bs = blockIdx.x;
    int b = bs >> 11, s = bs & (SS - 1);
    int lane = threadIdx.x & 31, h = threadIdx.x >> 5;
    const float* yp = g_yout + (size_t)((b * SS + s) * NH + h) * DH;
    float4 v0 = ((const float4*)yp)[lane * 2];
    float4 v1 = ((const float4*)yp)[lane * 2 + 1];
    float sum = v0.x + v0.y + v0.z + v0.w + v1.x + v1.y + v1.z + v1.w;
    float sq = v0.x * v0.x + v0.y * v0.y + v0.z * v0.z + v0.w * v0.w +
               v1.x * v1.x + v1.y * v1.y + v1.z * v1.z + v1.w * v1.w;
#pragma unroll
    for (int o = 16; o; o >>= 1) {
        sum += __shfl_xor_sync(0xffffffffu, sum, o);
        sq += __shfl_xor_sync(0xffffffffu, sq, o);
    }
    float mean = sum * (1.f / DH);
    float var = sq * (1.f / DH) - mean * mean;
    float rs = rsqrtf(var + 1e-6f);
    int dbase = h * DH + lane * 8;
    float4 sc0 = ((const float4*)(gsc + dbase))[0];
    float4 sc1 = ((const float4*)(gsc + dbase))[1];
    float4 bi0 = ((const float4*)(gbi + dbase))[0];
    float4 bi1 = ((const float4*)(gbi + dbase))[1];
    float* op = out + (size_t)(b * SS + s) * DD + dbase;
    float4 o0, o1;
    o0.x = (v0.x - mean) * rs * sc0.x + bi0.x;
    o0.y = (v0.y - mean) * rs * sc0.y + bi0.y;
    o0.z = (v0.z - mean) * rs * sc0.z + bi0.z;
    o0.w = (v0.w - mean) * rs * sc0.w + bi0.w;
    o1.x = (v1.x - mean) * rs * sc1.x + bi1.x;
    o1.y = (v1.y - mean) * rs * sc1.y + bi1.y;
    o1.z = (v1.z - mean) * rs * sc1.z + bi1.z;
    o1.w = (v1.w - mean) * rs * sc1.w + bi1.w;
    ((float4*)op)[0] = o0;
    ((float4*)op)[1] = o1;
}

// ---------------- launch ----------------
extern "C" void kernel_launch(void* const* d_in, const int* in_sizes, int n_in,
                              void* d_out, int out_size) {
    const float* x   = (const float*)d_in[0];
    const float* ck  = (const float*)d_in[1];
    const float* cb  = (const float*)d_in[2];
    const float* w_i = (const float*)d_in[3];
    const float* w_f = (const float*)d_in[4];
    const float* w_z = (const float*)d_in[5];
    const float* w_o = (const float*)d_in[6];
    const float* wr  = (const float*)d_in[7];
    const float* rb  = (const float*)d_in[8];
    const float* gsc = (const float*)d_in[9];
    const float* gbi = (const float*)d_in[10];
    float* out = (float*)d_out;

    conv_swish_k<<<BB * SS, 256>>>(x, ck, cb);
    dim3 gg(16, 8, 16);
    gates_gemm_k<<<gg, 256>>>(x, w_i, w_f, w_z, w_o);
    dim3 gr(NSLICE, NH * BB);  // 16 clusters of 8 CTAs: one cluster per (h,b)
    rec_k<<<gr, 256>>>(wr, rb);
    gnorm_k<<<BB * SS, 128>>>(gsc, gbi, out);
}

// round 13
// speedup vs baseline: 1.7024x; 1.1097x over previous
// Round 13: r10's proven 4-cluster skeleton (8 CTAs/head, 4 batches merged, split
// cluster arrive/wait + DSMEM pushes) + MUFU pointwise (r11/r12-proven precision)
// + software-pipelined gate prefetch (hides DRAM latency on the pace-setting CTA).
#include <cuda_runtime.h>
#include <math.h>
#include <stdint.h>

#define BB 4
#define SS 2048
#define DD 1024
#define NH 4
#define DH 256
#define KK 4
#define NSLICE 8

typedef unsigned long long u64;

// ---------------- scratch (static device arrays; no allocation) ----------------
__device__ float g_xconv[BB * SS * DD];            // 33.5M floats
__device__ float g_gates[SS * NH * 4 * BB * DH];   // [t][h][g][b][e]
__device__ float g_yout [BB * SS * NH * DH];       // [b][t][h][e]

// ---------------- helpers ----------------
__device__ __forceinline__ u64 pk2(float a, float b) {
    u64 r; asm("mov.b64 %0,{%1,%2};" : "=l"(r) : "f"(a), "f"(b)); return r;
}
__device__ __forceinline__ u64 f2fma(u64 a, u64 b, u64 c) {
    u64 d; asm("fma.rn.f32x2 %0,%1,%2,%3;" : "=l"(d) : "l"(a), "l"(b), "l"(c)); return d;
}
__device__ __forceinline__ float f2lo(u64 v) { return __uint_as_float((unsigned)v); }
__device__ __forceinline__ float f2hi(u64 v) { return __uint_as_float((unsigned)(v >> 32)); }
__device__ __forceinline__ uint32_t smem_u32(const void* p) {
    uint32_t a;
    asm("{ .reg .u64 t; cvta.to.shared.u64 t, %1; cvt.u32.u64 %0, t; }" : "=r"(a) : "l"(p));
    return a;
}
__device__ __forceinline__ void sts_cluster_f32(uint32_t local_addr, int rank, float v) {
    uint32_t ra;
    asm volatile("mapa.shared::cluster.u32 %0, %1, %2;" : "=r"(ra) : "r"(local_addr), "r"(rank));
    asm volatile("st.shared::cluster.f32 [%0], %1;" :: "r"(ra), "f"(v) : "memory");
}
#define CLUSTER_ARRIVE() asm volatile("barrier.cluster.arrive.aligned;" ::: "memory")
#define CLUSTER_WAIT()   asm volatile("barrier.cluster.wait.aligned;" ::: "memory")

// ---------------- causal depthwise conv (K=4) + swish ----------------
__global__ void conv_swish_k(const float* __restrict__ x,
                             const float* __restrict__ ck,
                             const float* __restrict__ cb) {
    int bs = blockIdx.x;
    int b = bs >> 11, s = bs & (SS - 1);
    int q = threadIdx.x;  // d-quad 0..255
    const float4* x4 = (const float4*)x;
    const float4* k4 = (const float4*)ck;
    float4 k0 = k4[0 * (DD / 4) + q];
    float4 k1 = k4[1 * (DD / 4) + q];
    float4 k2 = k4[2 * (DD / 4) + q];
    float4 k3 = k4[3 * (DD / 4) + q];
    float4 acc = ((const float4*)cb)[q];
    int rowq = (b * SS + s) * (DD / 4);
#define CONV_TAP(kk, kv)                                            \
    { int sr = s - 3 + (kk);                                        \
      if (sr >= 0) {                                                \
          float4 xv = x4[(b * SS + sr) * (DD / 4) + q];             \
          acc.x += (kv).x * xv.x; acc.y += (kv).y * xv.y;           \
          acc.z += (kv).z * xv.z; acc.w += (kv).w * xv.w; } }
    CONV_TAP(0, k0) CONV_TAP(1, k1) CONV_TAP(2, k2) CONV_TAP(3, k3)
#undef CONV_TAP
    float4 r;
    r.x = acc.x / (1.f + expf(-acc.x));
    r.y = acc.y / (1.f + expf(-acc.y));
    r.z = acc.z / (1.f + expf(-acc.z));
    r.w = acc.w / (1.f + expf(-acc.w));
    ((float4*)g_xconv)[rowq + q] = r;
}

// ---------------- gate GEMMs: gates[t][h][g][b][e]  (packed f32x2 FMA) ----------------
__global__ void __launch_bounds__(256, 1)
gates_gemm_k(const float* __restrict__ x,
             const float* __restrict__ w_i, const float* __restrict__ w_f,
             const float* __restrict__ w_z, const float* __restrict__ w_o) {
    int h = blockIdx.z >> 2, g = blockIdx.z & 3;
    int b = blockIdx.y >> 1, eh = blockIdx.y & 1;
    int sch = blockIdx.x;
    const float* in = (g < 2) ? g_xconv : x;
    const float* W = (g == 0) ? w_i : (g == 1) ? w_f : (g == 2) ? w_z : w_o;

    int tid = threadIdx.x, lane = tid & 31, wid = tid >> 5;
    int el = wid * 16 + (lane & 15);
    int dh = lane >> 4;
    int eg = eh * 128 + el;
    int dbase = dh * 128;

    ulonglong2 wq[32];
#pragma unroll
    for (int j = 0; j < 32; j++) {
        const float* p = W + (size_t)(h * DH + dbase + 4 * j) * DH + eg;
        wq[j].x = pk2(p[0], p[DH]);
        wq[j].y = pk2(p[2 * DH], p[3 * DH]);
    }

    __shared__ __align__(16) float As[32][256];

    for (int tt = 0; tt < 4; tt++) {
        int s0 = (sch * 4 + tt) * 32;
        for (int l = tid; l < 32 * 64; l += 256) {
            int r = l >> 6, q = l & 63;
            ((float4*)As[r])[q] =
                ((const float4*)(in + (size_t)(b * SS + s0 + r) * DD + h * DH))[q];
        }
        __syncthreads();
#pragma unroll 1
        for (int r = 0; r < 32; r++) {
            u64 al = 0, ah = 0;
#pragma unroll
            for (int j = 0; j < 32; j++) {
                ulonglong2 av = *(const ulonglong2*)&As[r][dbase + 4 * j];
                al = f2fma(wq[j].x, av.x, al);
                ah = f2fma(wq[j].y, av.y, ah);
            }
            float sum = (f2lo(al) + f2hi(al)) + (f2lo(ah) + f2hi(ah));
            sum += __shfl_xor_sync(0xffffffffu, sum, 16);
            if (dh == 0)
                g_gates[(size_t)(((s0 + r) * NH + h) * 4 + g) * (BB * DH) + b * DH + eg] = sum;
        }
        __syncthreads();
    }
}

// ---------------- recurrence: 4 clusters (one per head), 8 CTAs each ----------------
__global__ void __launch_bounds__(256, 1) __cluster_dims__(NSLICE, 1, 1)
rec_k(const float* __restrict__ Wr, const float* __restrict__ rb) {
    int h = blockIdx.y, si = blockIdx.x;  // si == cluster rank
    int tid = threadIdx.x, lane = tid & 31, wid = tid >> 5;
    int g = wid & 3, ehi = wid >> 2;
    int dh = lane >> 4;
    int e = ehi * 16 + (lane & 15);
    int eg = si * 32 + e;
    int dbase = dh * 128;

    // packed recurrent weights: W[h][d][g][eg], pairs (d,d+1); stride 4*DH per d
    ulonglong2 wq[32];
#pragma unroll
    for (int j = 0; j < 32; j++) {
        const float* p = Wr + (size_t)((h * DH + dbase + 4 * j) * 4 + g) * DH + eg;
        wq[j].x = pk2(p[0], p[4 * DH]);
        wq[j].y = pk2(p[8 * DH], p[12 * DH]);
    }

    // state threads: tid<128 -> (b, e)
    int sb = tid >> 5;
    int se = tid & 31;
    int seg = si * 32 + se;
    float bI = 0, bF = 0, bZ = 0, bO = 0, c = 0, n = 0, m = 0;
    if (tid < 128) {
        bI = rb[(0 * NH + h) * DH + seg];
        bF = rb[(1 * NH + h) * DH + seg];
        bZ = rb[(2 * NH + h) * DH + seg];
        bO = rb[(3 * NH + h) * DH + seg];
    }

    __shared__ __align__(16) float y_s[2][BB][DH];
    __shared__ float raw_s[4][BB][32];

    for (int i = tid; i < BB * DH / 4; i += 256)
        ((float4*)&y_s[0][0][0])[i] = make_float4(0.f, 0.f, 0.f, 0.f);
    CLUSTER_ARRIVE();  // paired with wait at top of t=0

    uint32_t ya0 = 0, ya1 = 0;
    if (tid < 128) {
        ya0 = smem_u32(&y_s[0][sb][seg]);
        ya1 = smem_u32(&y_s[1][sb][seg]);
    }

    // software-pipelined gate inputs: preload step 0
    float gI = 0, gF = 0, gZ = 0, gO = 0;
    if (tid < 128) {
        const float* gp = g_gates + (size_t)(0 * NH + h) * 4 * (BB * DH) + sb * DH + seg;
        gI = gp[0];
        gF = gp[BB * DH];
        gZ = gp[2 * BB * DH];
        gO = gp[3 * BB * DH];
    }

    for (int t = 0; t < SS; t++) {
        int rd = t & 1;
        CLUSTER_WAIT();  // all pushes into y_s[rd] complete (pairs with prior arrive)

        // 4-batch matvec over this thread's 128-d half, packed f32x2
        u64 a0l = 0, a0h = 0, a1l = 0, a1h = 0, a2l = 0, a2h = 0, a3l = 0, a3h = 0;
#pragma unroll
        for (int j = 0; j < 32; j++) {
            ulonglong2 wv = wq[j];
            ulonglong2 y0 = *(const ulonglong2*)&y_s[rd][0][dbase + 4 * j];
            a0l = f2fma(wv.x, y0.x, a0l); a0h = f2fma(wv.y, y0.y, a0h);
            ulonglong2 y1 = *(const ulonglong2*)&y_s[rd][1][dbase + 4 * j];
            a1l = f2fma(wv.x, y1.x, a1l); a1h = f2fma(wv.y, y1.y, a1h);
            ulonglong2 y2 = *(const ulonglong2*)&y_s[rd][2][dbase + 4 * j];
            a2l = f2fma(wv.x, y2.x, a2l); a2h = f2fma(wv.y, y2.y, a2h);
            ulonglong2 y3 = *(const ulonglong2*)&y_s[rd][3][dbase + 4 * j];
            a3l = f2fma(wv.x, y3.x, a3l); a3h = f2fma(wv.y, y3.y, a3h);
        }
        float r0 = (f2lo(a0l) + f2hi(a0l)) + (f2lo(a0h) + f2hi(a0h));
        float r1 = (f2lo(a1l) + f2hi(a1l)) + (f2lo(a1h) + f2hi(a1h));
        float r2 = (f2lo(a2l) + f2hi(a2l)) + (f2lo(a2h) + f2hi(a2h));
        float r3 = (f2lo(a3l) + f2hi(a3l)) + (f2lo(a3h) + f2hi(a3h));
        r0 += __shfl_xor_sync(0xffffffffu, r0, 16);
        r1 += __shfl_xor_sync(0xffffffffu, r1, 16);
        r2 += __shfl_xor_sync(0xffffffffu, r2, 16);
        r3 += __shfl_xor_sync(0xffffffffu, r3, 16);
        if (dh == 0) {
            raw_s[g][0][e] = r0;
            raw_s[g][1][e] = r1;
            raw_s[g][2][e] = r2;
            raw_s[g][3][e] = r3;
        }
        __syncthreads();

        if (tid < 128) {
            float rI = raw_s[0][sb][se] + gI + bI;
            float rF = raw_s[1][sb][se] + gF + bF;
            float rZ = raw_s[2][sb][se] + gZ + bZ;
            float rO = raw_s[3][sb][se] + gO + bO;

            // current gates consumed -> issue next step's loads now (hidden behind
            // the remainder of this step + next step's wait + matvec)
            if (t + 1 < SS) {
                const float* gp =
                    g_gates + (size_t)((t + 1) * NH + h) * 4 * (BB * DH) + sb * DH + seg;
                gI = gp[0];
                gF = gp[BB * DH];
                gZ = gp[2 * BB * DH];
                gO = gp[3 * BB * DH];
            }

            // MUFU stabilized update (precision proven r11/r12: rel_err 3.7e-7)
            float lsf = fminf(rF, 0.f) - __logf(1.f + __expf(-fabsf(rF)));
            float lfm = m + lsf;
            float mn = fmaxf(rI, lfm);
            float ig = __expf(rI - mn);
            float fg = __expf(lfm - mn);
            float tz = 1.f - 2.f / (1.f + __expf(2.f * rZ));  // tanh(rZ)
            c = fg * c + ig * tz;
            n = fg * n + ig;
            m = mn;
            float yv = (c / n) / (1.f + __expf(-rO));

            uint32_t dst = rd ? ya0 : ya1;
#pragma unroll
            for (int r = 0; r < NSLICE; r++)
                sts_cluster_f32(dst, r, yv);
            g_yout[(size_t)((sb * SS + t) * NH + h) * DH + seg] = yv;
        }
        CLUSTER_ARRIVE();  // release: step-t pushes visible after peers' next wait
    }
    CLUSTER_WAIT();  // balance final arrive; no exit under in-flight DSMEM stores
}

// ---------------- per-head GroupNorm + affine ----------------
__global__ void gnorm_k(const float* __restrict__ gsc,
                        const float* __restrict__ gbi,
                        float* __restrict__ out) {
    int bs = blockIdx.x;
    int b = bs >> 11, s = bs & (SS - 1);
    int lane = threadIdx.x & 31, h = threadIdx.x >> 5;
    const float* yp = g_yout + (size_t)((b * SS + s) * NH + h) * DH;
    float4 v0 = ((const float4*)yp)[lane * 2];
    float4 v1 = ((const float4*)yp)[lane * 2 + 1];
    float sum = v0.x + v0.y + v0.z + v0.w + v1.x + v1.y + v1.z + v1.w;
    float sq = v0.x * v0.x + v0.y * v0.y + v0.z * v0.z + v0.w * v0.w +
               v1.x * v1.x + v1.y * v1.y + v1.z * v1.z + v1.w * v1.w;
#pragma unroll
    for (int o = 16; o; o >>= 1) {
        sum += __shfl_xor_sync(0xffffffffu, sum, o);
        sq += __shfl_xor_sync(0xffffffffu, sq, o);
    }
    float mean = sum * (1.f / DH);
    float var = sq * (1.f / DH) - mean * mean;
    float rs = rsqrtf(var + 1e-6f);
    int dbase = h * DH + lane * 8;
    float4 sc0 = ((const float4*)(gsc + dbase))[0];
    float4 sc1 = ((const float4*)(gsc + dbase))[1];
    float4 bi0 = ((const float4*)(gbi + dbase))[0];
    float4 bi1 = ((const float4*)(gbi + dbase))[1];
    float* op = out + (size_t)(b * SS + s) * DD + dbase;
    float4 o0, o1;
    o0.x = (v0.x - mean) * rs * sc0.x + bi0.x;
    o0.y = (v0.y - mean) * rs * sc0.y + bi0.y;
    o0.z = (v0.z - mean) * rs * sc0.z + bi0.z;
    o0.w = (v0.w - mean) * rs * sc0.w + bi0.w;
    o1.x = (v1.x - mean) * rs * sc1.x + bi1.x;
    o1.y = (v1.y - mean) * rs * sc1.y + bi1.y;
    o1.z = (v1.z - mean) * rs * sc1.z + bi1.z;
    o1.w = (v1.w - mean) * rs * sc1.w + bi1.w;
    ((float4*)op)[0] = o0;
    ((float4*)op)[1] = o1;
}

// ---------------- launch ----------------
extern "C" void kernel_launch(void* const* d_in, const int* in_sizes, int n_in,
                              void* d_out, int out_size) {
    const float* x   = (const float*)d_in[0];
    const float* ck  = (const float*)d_in[1];
    const float* cb  = (const float*)d_in[2];
    const float* w_i = (const float*)d_in[3];
    const float* w_f = (const float*)d_in[4];
    const float* w_z = (const float*)d_in[5];
    const float* w_o = (const float*)d_in[6];
    const float* wr  = (const float*)d_in[7];
    const float* rb  = (const float*)d_in[8];
    const float* gsc = (const float*)d_in[9];
    const float* gbi = (const float*)d_in[10];
    float* out = (float*)d_out;

    conv_swish_k<<<BB * SS, 256>>>(x, ck, cb);
    dim3 gg(16, 8, 16);
    gates_gemm_k<<<gg, 256>>>(x, w_i, w_f, w_z, w_o);
    dim3 gr(NSLICE, NH);  // 4 clusters of 8 CTAs: one cluster per head
    rec_k<<<gr, 256>>>(wr, rb);
    gnorm_k<<<BB * SS, 128>>>(gsc, gbi, out);
}

// round 14
// speedup vs baseline: 1.7072x; 1.0028x over previous
// Round 14: shrink the cluster-barrier release-drain — g_yout STG moved after arrive;
// DSMEM pushes staged through smem and issued as rank-parallel packed b64 from all
// 256 threads (was 8 serialized scalar pushes from each of 128 threads).
// Everything else identical to r13 (MUFU pointwise, gate prefetch, 4 clusters x 8 CTAs).
#include <cuda_runtime.h>
#include <math.h>
#include <stdint.h>

#define BB 4
#define SS 2048
#define DD 1024
#define NH 4
#define DH 256
#define KK 4
#define NSLICE 8

typedef unsigned long long u64;

// ---------------- scratch (static device arrays; no allocation) ----------------
__device__ float g_xconv[BB * SS * DD];            // 33.5M floats
__device__ float g_gates[SS * NH * 4 * BB * DH];   // [t][h][g][b][e]
__device__ float g_yout [BB * SS * NH * DH];       // [b][t][h][e]

// ---------------- helpers ----------------
__device__ __forceinline__ u64 pk2(float a, float b) {
    u64 r; asm("mov.b64 %0,{%1,%2};" : "=l"(r) : "f"(a), "f"(b)); return r;
}
__device__ __forceinline__ u64 f2fma(u64 a, u64 b, u64 c) {
    u64 d; asm("fma.rn.f32x2 %0,%1,%2,%3;" : "=l"(d) : "l"(a), "l"(b), "l"(c)); return d;
}
__device__ __forceinline__ float f2lo(u64 v) { return __uint_as_float((unsigned)v); }
__device__ __forceinline__ float f2hi(u64 v) { return __uint_as_float((unsigned)(v >> 32)); }
__device__ __forceinline__ uint32_t smem_u32(const void* p) {
    uint32_t a;
    asm("{ .reg .u64 t; cvta.to.shared.u64 t, %1; cvt.u32.u64 %0, t; }" : "=r"(a) : "l"(p));
    return a;
}
__device__ __forceinline__ uint32_t mapa_u32(uint32_t local, int rank) {
    uint32_t r;
    asm("mapa.shared::cluster.u32 %0, %1, %2;" : "=r"(r) : "r"(local), "r"(rank));
    return r;
}
__device__ __forceinline__ void sts_cluster_b64(uint32_t raddr, u64 v) {
    asm volatile("st.shared::cluster.b64 [%0], %1;" :: "r"(raddr), "l"(v) : "memory");
}
#define CLUSTER_ARRIVE() asm volatile("barrier.cluster.arrive.aligned;" ::: "memory")
#define CLUSTER_WAIT()   asm volatile("barrier.cluster.wait.aligned;" ::: "memory")

// ---------------- causal depthwise conv (K=4) + swish ----------------
__global__ void conv_swish_k(const float* __restrict__ x,
                             const float* __restrict__ ck,
                             const float* __restrict__ cb) {
    int bs = blockIdx.x;
    int b = bs >> 11, s = bs & (SS - 1);
    int q = threadIdx.x;  // d-quad 0..255
    const float4* x4 = (const float4*)x;
    const float4* k4 = (const float4*)ck;
    float4 k0 = k4[0 * (DD / 4) + q];
    float4 k1 = k4[1 * (DD / 4) + q];
    float4 k2 = k4[2 * (DD / 4) + q];
    float4 k3 = k4[3 * (DD / 4) + q];
    float4 acc = ((const float4*)cb)[q];
    int rowq = (b * SS + s) * (DD / 4);
#define CONV_TAP(kk, kv)                                            \
    { int sr = s - 3 + (kk);                                        \
      if (sr >= 0) {                                                \
          float4 xv = x4[(b * SS + sr) * (DD / 4) + q];             \
          acc.x += (kv).x * xv.x; acc.y += (kv).y * xv.y;           \
          acc.z += (kv).z * xv.z; acc.w += (kv).w * xv.w; } }
    CONV_TAP(0, k0) CONV_TAP(1, k1) CONV_TAP(2, k2) CONV_TAP(3, k3)
#undef CONV_TAP
    float4 r;
    r.x = acc.x / (1.f + expf(-acc.x));
    r.y = acc.y / (1.f + expf(-acc.y));
    r.z = acc.z / (1.f + expf(-acc.z));
    r.w = acc.w / (1.f + expf(-acc.w));
    ((float4*)g_xconv)[rowq + q] = r;
}

// ---------------- gate GEMMs: gates[t][h][g][b][e]  (packed f32x2 FMA) ----------------
__global__ void __launch_bounds__(256, 1)
gates_gemm_k(const float* __restrict__ x,
             const float* __restrict__ w_i, const float* __restrict__ w_f,
             const float* __restrict__ w_z, const float* __restrict__ w_o) {
    int h = blockIdx.z >> 2, g = blockIdx.z & 3;
    int b = blockIdx.y >> 1, eh = blockIdx.y & 1;
    int sch = blockIdx.x;
    const float* in = (g < 2) ? g_xconv : x;
    const float* W = (g == 0) ? w_i : (g == 1) ? w_f : (g == 2) ? w_z : w_o;

    int tid = threadIdx.x, lane = tid & 31, wid = tid >> 5;
    int el = wid * 16 + (lane & 15);
    int dh = lane >> 4;
    int eg = eh * 128 + el;
    int dbase = dh * 128;

    ulonglong2 wq[32];
#pragma unroll
    for (int j = 0; j < 32; j++) {
        const float* p = W + (size_t)(h * DH + dbase + 4 * j) * DH + eg;
        wq[j].x = pk2(p[0], p[DH]);
        wq[j].y = pk2(p[2 * DH], p[3 * DH]);
    }

    __shared__ __align__(16) float As[32][256];

    for (int tt = 0; tt < 4; tt++) {
        int s0 = (sch * 4 + tt) * 32;
        for (int l = tid; l < 32 * 64; l += 256) {
            int r = l >> 6, q = l & 63;
            ((float4*)As[r])[q] =
                ((const float4*)(in + (size_t)(b * SS + s0 + r) * DD + h * DH))[q];
        }
        __syncthreads();
#pragma unroll 1
        for (int r = 0; r < 32; r++) {
            u64 al = 0, ah = 0;
#pragma unroll
            for (int j = 0; j < 32; j++) {
                ulonglong2 av = *(const ulonglong2*)&As[r][dbase + 4 * j];
                al = f2fma(wq[j].x, av.x, al);
                ah = f2fma(wq[j].y, av.y, ah);
            }
            float sum = (f2lo(al) + f2hi(al)) + (f2lo(ah) + f2hi(ah));
            sum += __shfl_xor_sync(0xffffffffu, sum, 16);
            if (dh == 0)
                g_gates[(size_t)(((s0 + r) * NH + h) * 4 + g) * (BB * DH) + b * DH + eg] = sum;
        }
        __syncthreads();
    }
}

// ---------------- recurrence: 4 clusters (one per head), 8 CTAs each ----------------
__global__ void __launch_bounds__(256, 1) __cluster_dims__(NSLICE, 1, 1)
rec_k(const float* __restrict__ Wr, const float* __restrict__ rb) {
    int h = blockIdx.y, si = blockIdx.x;  // si == cluster rank
    int tid = threadIdx.x, lane = tid & 31, wid = tid >> 5;
    int g = wid & 3, ehi = wid >> 2;
    int dh = lane >> 4;
    int e = ehi * 16 + (lane & 15);
    int eg = si * 32 + e;
    int dbase = dh * 128;

    // packed recurrent weights: W[h][d][g][eg], pairs (d,d+1); stride 4*DH per d
    ulonglong2 wq[32];
#pragma unroll
    for (int j = 0; j < 32; j++) {
        const float* p = Wr + (size_t)((h * DH + dbase + 4 * j) * 4 + g) * DH + eg;
        wq[j].x = pk2(p[0], p[4 * DH]);
        wq[j].y = pk2(p[8 * DH], p[12 * DH]);
    }

    // state threads: tid<128 -> (b, e)
    int sb = tid >> 5;
    int se = tid & 31;
    int seg = si * 32 + se;
    float bI = 0, bF = 0, bZ = 0, bO = 0, c = 0, n = 0, m = 0;
    if (tid < 128) {
        bI = rb[(0 * NH + h) * DH + seg];
        bF = rb[(1 * NH + h) * DH + seg];
        bZ = rb[(2 * NH + h) * DH + seg];
        bO = rb[(3 * NH + h) * DH + seg];
    }

    __shared__ __align__(16) float y_s[2][BB][DH];
    __shared__ float raw_s[4][BB][32];
    __shared__ __align__(16) float y_stage[BB][32];  // this CTA's fresh y slice

    for (int i = tid; i < BB * DH / 4; i += 256)
        ((float4*)&y_s[0][0][0])[i] = make_float4(0.f, 0.f, 0.f, 0.f);
    CLUSTER_ARRIVE();  // paired with wait at top of t=0

    // push-plan for this thread: rank = tid>>5, two u64 chunks of the 128-float slice
    // chunk j in [0,64): source = y_stage viewed as u64[64]; dest (b,e-pair) derived from j
    int prank = tid >> 5;
    int k0i = tid & 31;        // chunk 1
    int k1i = k0i + 32;        // chunk 2
    const u64* stage_u64 = (const u64*)&y_stage[0][0];
    // local dest addresses for both chunks in both buffers, then mapa to my rank
    uint32_t d00 = 0, d01 = 0, d10 = 0, d11 = 0;
    {
        int b0 = k0i >> 4, p0 = (k0i & 15) * 2;
        int b1 = k1i >> 4, p1 = (k1i & 15) * 2;
        uint32_t l00 = smem_u32(&y_s[0][b0][si * 32 + p0]);
        uint32_t l01 = smem_u32(&y_s[0][b1][si * 32 + p1]);
        uint32_t l10 = smem_u32(&y_s[1][b0][si * 32 + p0]);
        uint32_t l11 = smem_u32(&y_s[1][b1][si * 32 + p1]);
        d00 = mapa_u32(l00, prank);
        d01 = mapa_u32(l01, prank);
        d10 = mapa_u32(l10, prank);
        d11 = mapa_u32(l11, prank);
    }

    // software-pipelined gate inputs: preload step 0
    float gI = 0, gF = 0, gZ = 0, gO = 0;
    if (tid < 128) {
        const float* gp = g_gates + (size_t)(0 * NH + h) * 4 * (BB * DH) + sb * DH + seg;
        gI = gp[0];
        gF = gp[BB * DH];
        gZ = gp[2 * BB * DH];
        gO = gp[3 * BB * DH];
    }

    float yv = 0.f;  // carried for post-arrive STG

    for (int t = 0; t < SS; t++) {
        int rd = t & 1;
        CLUSTER_WAIT();  // all pushes into y_s[rd] complete (pairs with prior arrive)

        // 4-batch matvec over this thread's 128-d half, packed f32x2
        u64 a0l = 0, a0h = 0, a1l = 0, a1h = 0, a2l = 0, a2h = 0, a3l = 0, a3h = 0;
#pragma unroll
        for (int j = 0; j < 32; j++) {
            ulonglong2 wv = wq[j];
            ulonglong2 y0 = *(const ulonglong2*)&y_s[rd][0][dbase + 4 * j];
            a0l = f2fma(wv.x, y0.x, a0l); a0h = f2fma(wv.y, y0.y, a0h);
            ulonglong2 y1 = *(const ulonglong2*)&y_s[rd][1][dbase + 4 * j];
            a1l = f2fma(wv.x, y1.x, a1l); a1h = f2fma(wv.y, y1.y, a1h);
            ulonglong2 y2 = *(const ulonglong2*)&y_s[rd][2][dbase + 4 * j];
            a2l = f2fma(wv.x, y2.x, a2l); a2h = f2fma(wv.y, y2.y, a2h);
            ulonglong2 y3 = *(const ulonglong2*)&y_s[rd][3][dbase + 4 * j];
            a3l = f2fma(wv.x, y3.x, a3l); a3h = f2fma(wv.y, y3.y, a3h);
        }
        float r0 = (f2lo(a0l) + f2hi(a0l)) + (f2lo(a0h) + f2hi(a0h));
        float r1 = (f2lo(a1l) + f2hi(a1l)) + (f2lo(a1h) + f2hi(a1h));
        float r2 = (f2lo(a2l) + f2hi(a2l)) + (f2lo(a2h) + f2hi(a2h));
        float r3 = (f2lo(a3l) + f2hi(a3l)) + (f2lo(a3h) + f2hi(a3h));
        r0 += __shfl_xor_sync(0xffffffffu, r0, 16);
        r1 += __shfl_xor_sync(0xffffffffu, r1, 16);
        r2 += __shfl_xor_sync(0xffffffffu, r2, 16);
        r3 += __shfl_xor_sync(0xffffffffu, r3, 16);
        if (dh == 0) {
            raw_s[g][0][e] = r0;
            raw_s[g][1][e] = r1;
            raw_s[g][2][e] = r2;
            raw_s[g][3][e] = r3;
        }
        __syncthreads();

        if (tid < 128) {
            float rI = raw_s[0][sb][se] + gI + bI;
            float rF = raw_s[1][sb][se] + gF + bF;
            float rZ = raw_s[2][sb][se] + gZ + bZ;
            float rO = raw_s[3][sb][se] + gO + bO;

            // consume gates -> issue next step's loads (hidden behind rest of step)
            if (t + 1 < SS) {
                const float* gp =
                    g_gates + (size_t)((t + 1) * NH + h) * 4 * (BB * DH) + sb * DH + seg;
                gI = gp[0];
                gF = gp[BB * DH];
                gZ = gp[2 * BB * DH];
                gO = gp[3 * BB * DH];
            }

            // MUFU stabilized update (precision proven r11-r13: rel_err 3.72e-7)
            float lsf = fminf(rF, 0.f) - __logf(1.f + __expf(-fabsf(rF)));
            float lfm = m + lsf;
            float mn = fmaxf(rI, lfm);
            float ig = __expf(rI - mn);
            float fg = __expf(lfm - mn);
            float tz = 1.f - 2.f / (1.f + __expf(2.f * rZ));  // tanh(rZ)
            c = fg * c + ig * tz;
            n = fg * n + ig;
            m = mn;
            yv = (c / n) / (1.f + __expf(-rO));
            y_stage[sb][se] = yv;
        }
        __syncthreads();  // stage visible to all 8 warps

        // rank-parallel packed pushes: every thread sends 2x b64 to its one rank
        {
            u64 v0 = stage_u64[k0i];
            u64 v1 = stage_u64[k1i];
            if (rd) {  // wrote stage for buf rd^1 = 0
                sts_cluster_b64(d00, v0);
                sts_cluster_b64(d01, v1);
            } else {   // buf 1
                sts_cluster_b64(d10, v0);
                sts_cluster_b64(d11, v1);
            }
        }
        CLUSTER_ARRIVE();  // release: only smem/DSMEM stores in the drain set now

        // global y record AFTER arrive — off the release critical path
        if (tid < 128)
            g_yout[(size_t)((sb * SS + t) * NH + h) * DH + seg] = yv;
    }
    CLUSTER_WAIT();  // balance final arrive; no exit under in-flight DSMEM stores
}

// ---------------- per-head GroupNorm + affine ----------------
__global__ void gnorm_k(const float* __restrict__ gsc,
                        const float* __restrict__ gbi,
                        float* __restrict__ out) {
    int bs = blockIdx.x;
    int b = bs >> 11, s = bs & (SS - 1);
    int lane = threadIdx.x & 31, h = threadIdx.x >> 5;
    const float* yp = g_yout + (size_t)((b * SS + s) * NH + h) * DH;
    float4 v0 = ((const float4*)yp)[lane * 2];
    float4 v1 = ((const float4*)yp)[lane * 2 + 1];
    float sum = v0.x + v0.y + v0.z + v0.w + v1.x + v1.y + v1.z + v1.w;
    float sq = v0.x * v0.x + v0.y * v0.y + v0.z * v0.z + v0.w * v0.w +
               v1.x * v1.x + v1.y * v1.y + v1.z * v1.z + v1.w * v1.w;
#pragma unroll
    for (int o = 16; o; o >>= 1) {
        sum += __shfl_xor_sync(0xffffffffu, sum, o);
        sq += __shfl_xor_sync(0xffffffffu, sq, o);
    }
    float mean = sum * (1.f / DH);
    float var = sq * (1.f / DH) - mean * mean;
    float rs = rsqrtf(var + 1e-6f);
    int dbase = h * DH + lane * 8;
    float4 sc0 = ((const float4*)(gsc + dbase))[0];
    float4 sc1 = ((const float4*)(gsc + dbase))[1];
    float4 bi0 = ((const float4*)(gbi + dbase))[0];
    float4 bi1 = ((const float4*)(gbi + dbase))[1];
    float* op = out + (size_t)(b * SS + s) * DD + dbase;
    float4 o0, o1;
    o0.x = (v0.x - mean) * rs * sc0.x + bi0.x;
    o0.y = (v0.y - mean) * rs * sc0.y + bi0.y;
    o0.z = (v0.z - mean) * rs * sc0.z + bi0.z;
    o0.w = (v0.w - mean) * rs * sc0.w + bi0.w;
    o1.x = (v1.x - mean) * rs * sc1.x + bi1.x;
    o1.y = (v1.y - mean) * rs * sc1.y + bi1.y;
    o1.z = (v1.z - mean) * rs * sc1.z + bi1.z;
    o1.w = (v1.w - mean) * rs * sc1.w + bi1.w;
    ((float4*)op)[0] = o0;
    ((float4*)op)[1] = o1;
}

// ---------------- launch ----------------
extern "C" void kernel_launch(void* const* d_in, const int* in_sizes, int n_in,
                              void* d_out, int out_size) {
    const float* x   = (const float*)d_in[0];
    const float* ck  = (const float*)d_in[1];
    const float* cb  = (const float*)d_in[2];
    const float* w_i = (const float*)d_in[3];
    const float* w_f = (const float*)d_in[4];
    const float* w_z = (const float*)d_in[5];
    const float* w_o = (const float*)d_in[6];
    const float* wr  = (const float*)d_in[7];
    const float* rb  = (const float*)d_in[8];
    const float* gsc = (const float*)d_in[9];
    const float* gbi = (const float*)d_in[10];
    float* out = (float*)d_out;

    conv_swish_k<<<BB * SS, 256>>>(x, ck, cb);
    dim3 gg(16, 8, 16);
    gates_gemm_k<<<gg, 256>>>(x, w_i, w_f, w_z, w_o);
    dim3 gr(NSLICE, NH);  // 4 clusters of 8 CTAs: one cluster per head
    rec_k<<<gr, 256>>>(wr, rb);
    gnorm_k<<<BB * SS, 128>>>(gsc, gbi, out);
}

// round 15
// speedup vs baseline: 1.9722x; 1.1552x over previous
// Round 15: recurrence sync = 4-deep y ring + per-buffer full-mbarriers fed by 512B
// cluster bulk copies (8 tx events/step/CTA, vs r11's 1024 scalar st.async) — no empty
// barriers (read-completion is transitive through the full chain; max skew = 1 step).
// Replaces the whole-cluster barrier whose ~2400-cyc round trip floored r10/r13/r14.
#include <cuda_runtime.h>
#include <math.h>
#include <stdint.h>

#define BB 4
#define SS 2048
#define DD 1024
#define NH 4
#define DH 256
#define KK 4
#define NSLICE 8
#define NBUF 4

typedef unsigned long long u64;

// ---------------- scratch (static device arrays; no allocation) ----------------
__device__ float g_xconv[BB * SS * DD];            // 33.5M floats
__device__ float g_gates[SS * NH * 4 * BB * DH];   // [t][h][g][b][e]
__device__ float g_yout [BB * SS * NH * DH];       // [b][t][h][e]

// ---------------- helpers ----------------
__device__ __forceinline__ u64 pk2(float a, float b) {
    u64 r; asm("mov.b64 %0,{%1,%2};" : "=l"(r) : "f"(a), "f"(b)); return r;
}
__device__ __forceinline__ u64 f2fma(u64 a, u64 b, u64 c) {
    u64 d; asm("fma.rn.f32x2 %0,%1,%2,%3;" : "=l"(d) : "l"(a), "l"(b), "l"(c)); return d;
}
__device__ __forceinline__ float f2lo(u64 v) { return __uint_as_float((unsigned)v); }
__device__ __forceinline__ float f2hi(u64 v) { return __uint_as_float((unsigned)(v >> 32)); }
__device__ __forceinline__ uint32_t smem_u32(const void* p) {
    uint32_t a;
    asm("{ .reg .u64 t; cvta.to.shared.u64 t, %1; cvt.u32.u64 %0, t; }" : "=r"(a) : "l"(p));
    return a;
}
__device__ __forceinline__ uint32_t mapa_u32(uint32_t local, int rank) {
    uint32_t r;
    asm("mapa.shared::cluster.u32 %0, %1, %2;" : "=r"(r) : "r"(local), "r"(rank));
    return r;
}
__device__ __forceinline__ void mbar_init(uint32_t a, unsigned cnt) {
    asm volatile("mbarrier.init.shared.b64 [%0], %1;" :: "r"(a), "r"(cnt) : "memory");
}
__device__ __forceinline__ void mbar_arm_tx(uint32_t a, unsigned tx) {
    asm volatile("mbarrier.arrive.expect_tx.shared.b64 _, [%0], %1;" :: "r"(a), "r"(tx) : "memory");
}
__device__ __forceinline__ void mbar_wait(uint32_t a, unsigned parity) {
    unsigned done;
    asm volatile(
        "{\n\t.reg .pred p;\n\t"
        "mbarrier.try_wait.parity.acquire.cluster.shared::cta.b64 p, [%1], %2;\n\t"
        "selp.b32 %0, 1, 0, p;\n\t}"
        : "=r"(done) : "r"(a), "r"(parity) : "memory");
    while (!done) {
        asm volatile(
            "{\n\t.reg .pred p;\n\t"
            "mbarrier.try_wait.parity.acquire.cluster.shared::cta.b64 p, [%1], %2, 0x989680;\n\t"
            "selp.b32 %0, 1, 0, p;\n\t}"
            : "=r"(done) : "r"(a), "r"(parity) : "memory");
    }
}
__device__ __forceinline__ void bulk_copy_cluster(uint32_t dst, uint32_t src,
                                                  unsigned bytes, uint32_t rmbar) {
    asm volatile(
        "cp.async.bulk.shared::cluster.shared::cta.mbarrier::complete_tx::bytes "
        "[%0], [%1], %2, [%3];"
        :: "r"(dst), "r"(src), "r"(bytes), "r"(rmbar) : "memory");
}
#define FENCE_PROXY_ASYNC() asm volatile("fence.proxy.async.shared::cta;" ::: "memory")
#define CLUSTER_SYNC() do { \
    asm volatile("barrier.cluster.arrive.aligned;" ::: "memory"); \
    asm volatile("barrier.cluster.wait.aligned;" ::: "memory"); } while (0)

// ---------------- causal depthwise conv (K=4) + swish ----------------
__global__ void conv_swish_k(const float* __restrict__ x,
                             const float* __restrict__ ck,
                             const float* __restrict__ cb) {
    int bs = blockIdx.x;
    int b = bs >> 11, s = bs & (SS - 1);
    int q = threadIdx.x;  // d-quad 0..255
    const float4* x4 = (const float4*)x;
    const float4* k4 = (const float4*)ck;
    float4 k0 = k4[0 * (DD / 4) + q];
    float4 k1 = k4[1 * (DD / 4) + q];
    float4 k2 = k4[2 * (DD / 4) + q];
    float4 k3 = k4[3 * (DD / 4) + q];
    float4 acc = ((const float4*)cb)[q];
    int rowq = (b * SS + s) * (DD / 4);
#define CONV_TAP(kk, kv)                                            \
    { int sr = s - 3 + (kk);                                        \
      if (sr >= 0) {                                                \
          float4 xv = x4[(b * SS + sr) * (DD / 4) + q];             \
          acc.x += (kv).x * xv.x; acc.y += (kv).y * xv.y;           \
          acc.z += (kv).z * xv.z; acc.w += (kv).w * xv.w; } }
    CONV_TAP(0, k0) CONV_TAP(1, k1) CONV_TAP(2, k2) CONV_TAP(3, k3)
#undef CONV_TAP
    float4 r;
    r.x = acc.x / (1.f + expf(-acc.x));
    r.y = acc.y / (1.f + expf(-acc.y));
    r.z = acc.z / (1.f + expf(-acc.z));
    r.w = acc.w / (1.f + expf(-acc.w));
    ((float4*)g_xconv)[rowq + q] = r;
}

// ---------------- gate GEMMs: gates[t][h][g][b][e]  (packed f32x2 FMA) ----------------
__global__ void __launch_bounds__(256, 1)
gates_gemm_k(const float* __restrict__ x,
             const float* __restrict__ w_i, const float* __restrict__ w_f,
             const float* __restrict__ w_z, const float* __restrict__ w_o) {
    int h = blockIdx.z >> 2, g = blockIdx.z & 3;
    int b = blockIdx.y >> 1, eh = blockIdx.y & 1;
    int sch = blockIdx.x;
    const float* in = (g < 2) ? g_xconv : x;
    const float* W = (g == 0) ? w_i : (g == 1) ? w_f : (g == 2) ? w_z : w_o;

    int tid = threadIdx.x, lane = tid & 31, wid = tid >> 5;
    int el = wid * 16 + (lane & 15);
    int dh = lane >> 4;
    int eg = eh * 128 + el;
    int dbase = dh * 128;

    ulonglong2 wq[32];
#pragma unroll
    for (int j = 0; j < 32; j++) {
        const float* p = W + (size_t)(h * DH + dbase + 4 * j) * DH + eg;
        wq[j].x = pk2(p[0], p[DH]);
        wq[j].y = pk2(p[2 * DH], p[3 * DH]);
    }

    __shared__ __align__(16) float As[32][256];

    for (int tt = 0; tt < 4; tt++) {
        int s0 = (sch * 4 + tt) * 32;
        for (int l = tid; l < 32 * 64; l += 256) {
            int r = l >> 6, q = l & 63;
            ((float4*)As[r])[q] =
                ((const float4*)(in + (size_t)(b * SS + s0 + r) * DD + h * DH))[q];
        }
        __syncthreads();
#pragma unroll 1
        for (int r = 0; r < 32; r++) {
            u64 al = 0, ah = 0;
#pragma unroll
            for (int j = 0; j < 32; j++) {
                ulonglong2 av = *(const ulonglong2*)&As[r][dbase + 4 * j];
                al = f2fma(wq[j].x, av.x, al);
                ah = f2fma(wq[j].y, av.y, ah);
            }
            float sum = (f2lo(al) + f2hi(al)) + (f2lo(ah) + f2hi(ah));
            sum += __shfl_xor_sync(0xffffffffu, sum, 16);
            if (dh == 0)
                g_gates[(size_t)(((s0 + r) * NH + h) * 4 + g) * (BB * DH) + b * DH + eg] = sum;
        }
        __syncthreads();
    }
}

// ---------------- recurrence: 4 clusters, 4-deep ring + bulk-copy mbarrier pipeline ----
__global__ void __launch_bounds__(256, 1) __cluster_dims__(NSLICE, 1, 1)
rec_k(const float* __restrict__ Wr, const float* __restrict__ rb) {
    int h = blockIdx.y, si = blockIdx.x;  // si == cluster rank
    int tid = threadIdx.x, lane = tid & 31, wid = tid >> 5;
    int g = wid & 3, ehi = wid >> 2;
    int dh = lane >> 4;
    int e = ehi * 16 + (lane & 15);
    int eg = si * 32 + e;
    int dbase = dh * 128;

    // packed recurrent weights: W[h][d][g][eg], pairs (d,d+1); stride 4*DH per d
    ulonglong2 wq[32];
#pragma unroll
    for (int j = 0; j < 32; j++) {
        const float* p = Wr + (size_t)((h * DH + dbase + 4 * j) * 4 + g) * DH + eg;
        wq[j].x = pk2(p[0], p[4 * DH]);
        wq[j].y = pk2(p[8 * DH], p[12 * DH]);
    }

    // state threads: tid<128 -> (b, e)
    int sb = tid >> 5;
    int se = tid & 31;
    int seg = si * 32 + se;
    float bI = 0, bF = 0, bZ = 0, bO = 0, c = 0, n = 0, m = 0;
    if (tid < 128) {
        bI = rb[(0 * NH + h) * DH + seg];
        bF = rb[(1 * NH + h) * DH + seg];
        bZ = rb[(2 * NH + h) * DH + seg];
        bO = rb[(3 * NH + h) * DH + seg];
    }

    // y ring: [buf][slice][batch][32] — each CTA's slice = contiguous 512B block
    __shared__ __align__(1024) float y_s[NBUF][NSLICE][BB][32];
    __shared__ float raw_s[4][BB][32];
    __shared__ __align__(16) float y_stage[BB][32];   // fresh y slice, [batch][32] = 512B
    __shared__ __align__(8) u64 mb[NBUF];             // full[buf] mbarriers

    const unsigned BUFB = NSLICE * BB * 32 * 4;       // 4096 bytes per buffer
    const unsigned TXB = NSLICE * 512;                // 4096 tx bytes per fill

    uint32_t mb0 = smem_u32(&mb[0]);
    if (tid == 0) {
#pragma unroll
        for (int k = 0; k < NBUF; k++) {
            mbar_init(mb0 + 8 * k, 1);
            mbar_arm_tx(mb0 + 8 * k, TXB);   // pre-arm: buf k first filled for step k (k>0) / k+4 (k=0)
        }
    }
    for (int i = tid; i < (int)(BUFB / 16); i += 256)  // zero buffer 0 (read at t=0)
        ((float4*)&y_s[0][0][0][0])[i] = make_float4(0.f, 0.f, 0.f, 0.f);
    __syncthreads();
    CLUSTER_SYNC();  // barriers armed + buf0 zeroed everywhere before any pushes

    // remote bases (mapa is offset-preserving: add k*BUFB / 8*k for buffer selection)
    uint32_t dstB[NSLICE], mbB[NSLICE];
    uint32_t myBlk = smem_u32(&y_s[0][si][0][0]);
    uint32_t stg = smem_u32(&y_stage[0][0]);
#pragma unroll
    for (int r = 0; r < NSLICE; r++) {
        dstB[r] = mapa_u32(myBlk, r);
        mbB[r] = mapa_u32(mb0, r);
    }

    // software-pipelined gate inputs: preload step 0
    float gI = 0, gF = 0, gZ = 0, gO = 0;
    if (tid < 128) {
        const float* gp = g_gates + (size_t)(0 * NH + h) * 4 * (BB * DH) + sb * DH + seg;
        gI = gp[0];
        gF = gp[BB * DH];
        gZ = gp[2 * BB * DH];
        gO = gp[3 * BB * DH];
    }

    unsigned ph = 0;   // per-buffer parity bits
    float yv = 0.f;

    for (int t = 0; t < SS; t++) {
        int k = t & (NBUF - 1);
        if (t > 0) {
            mbar_wait(mb0 + 8 * k, (ph >> k) & 1u);
            ph ^= 1u << k;
            if (tid == 0) mbar_arm_tx(mb0 + 8 * k, TXB);  // re-arm for use at t+4 (safe: peers
                                                          // can't push y(t+4) before my y(t+3))
        }

        // 4-batch matvec, packed f32x2; same value order as r10-r14 (bit-identical)
        const float* ybk = &y_s[k][dh * 4][0][0];  // my d-half = slices dh*4 .. dh*4+3
        u64 a0l = 0, a0h = 0, a1l = 0, a1h = 0, a2l = 0, a2h = 0, a3l = 0, a3h = 0;
#pragma unroll
        for (int j = 0; j < 32; j++) {
            int off = (j >> 3) * (BB * 32) + 4 * (j & 7);  // slice-major remap of d = dbase+4j
            ulonglong2 wv = wq[j];
            ulonglong2 y0 = *(const ulonglong2*)&ybk[off + 0 * 32];
            a0l = f2fma(wv.x, y0.x, a0l); a0h = f2fma(wv.y, y0.y, a0h);
            ulonglong2 y1 = *(const ulonglong2*)&ybk[off + 1 * 32];
            a1l = f2fma(wv.x, y1.x, a1l); a1h = f2fma(wv.y, y1.y, a1h);
            ulonglong2 y2 = *(const ulonglong2*)&ybk[off + 2 * 32];
            a2l = f2fma(wv.x, y2.x, a2l); a2h = f2fma(wv.y, y2.y, a2h);
            ulonglong2 y3 = *(const ulonglong2*)&ybk[off + 3 * 32];
            a3l = f2fma(wv.x, y3.x, a3l); a3h = f2fma(wv.y, y3.y, a3h);
        }
        float r0 = (f2lo(a0l) + f2hi(a0l)) + (f2lo(a0h) + f2hi(a0h));
        float r1 = (f2lo(a1l) + f2hi(a1l)) + (f2lo(a1h) + f2hi(a1h));
        float r2 = (f2lo(a2l) + f2hi(a2l)) + (f2lo(a2h) + f2hi(a2h));
        float r3 = (f2lo(a3l) + f2hi(a3l)) + (f2lo(a3h) + f2hi(a3h));
        r0 += __shfl_xor_sync(0xffffffffu, r0, 16);
        r1 += __shfl_xor_sync(0xffffffffu, r1, 16);
        r2 += __shfl_xor_sync(0xffffffffu, r2, 16);
        r3 += __shfl_xor_sync(0xffffffffu, r3, 16);
        if (dh == 0) {
            raw_s[g][0][e] = r0;
            raw_s[g][1][e] = r1;
            raw_s[g][2][e] = r2;
            raw_s[g][3][e] = r3;
        }
        __syncthreads();

        if (tid < 128) {
            float rI = raw_s[0][sb][se] + gI + bI;
            float rF = raw_s[1][sb][se] + gF + bF;
            float rZ = raw_s[2][sb][se] + gZ + bZ;
            float rO = raw_s[3][sb][se] + gO + bO;

            // consume gates -> issue next step's loads (hidden behind rest of step)
            if (t + 1 < SS) {
                const float* gp =
                    g_gates + (size_t)((t + 1) * NH + h) * 4 * (BB * DH) + sb * DH + seg;
                gI = gp[0];
                gF = gp[BB * DH];
                gZ = gp[2 * BB * DH];
                gO = gp[3 * BB * DH];
            }

            // MUFU stabilized update (precision proven r11-r14: rel_err 3.72e-7)
            float lsf = fminf(rF, 0.f) - __logf(1.f + __expf(-fabsf(rF)));
            float lfm = m + lsf;
            float mn = fmaxf(rI, lfm);
            float ig = __expf(rI - mn);
            float fg = __expf(lfm - mn);
            float tz = 1.f - 2.f / (1.f + __expf(2.f * rZ));  // tanh(rZ)
            c = fg * c + ig * tz;
            n = fg * n + ig;
            m = mn;
            yv = (c / n) / (1.f + __expf(-rO));
            y_stage[sb][se] = yv;
        }
        __syncthreads();  // stage complete CTA-wide

        // broadcast my 512B slice to every rank's buf (t+1)&3 via bulk copies
        // (skip at the last step: y(SS) is never consumed)
        if (tid == 0 && t + 1 < SS) {
            FENCE_PROXY_ASYNC();  // stage stores -> async proxy
            int kn = (t + 1) & (NBUF - 1);
#pragma unroll
            for (int r = 0; r < NSLICE; r++)
                bulk_copy_cluster(dstB[r] + kn * BUFB, stg, 512, mbB[r] + 8 * kn);
        }

        // global y record — off the inter-CTA critical path
        if (tid < 128)
            g_yout[(size_t)((sb * SS + t) * NH + h) * DH + seg] = yv;
    }
    // all copies I issued were consumed by peers' waits (last push at t=SS-2, consumed
    // at t=SS-1); cluster sync guards against any exit-while-targeted corner
    CLUSTER_SYNC();
}

// ---------------- per-head GroupNorm + affine ----------------
__global__ void gnorm_k(const float* __restrict__ gsc,
                        const float* __restrict__ gbi,
                        float* __restrict__ out) {
    int bs = blockIdx.x;
    int b = bs >> 11, s = bs & (SS - 1);
    int lane = threadIdx.x & 31, h = threadIdx.x >> 5;
    const float* yp = g_yout + (size_t)((b * SS + s) * NH + h) * DH;
    float4 v0 = ((const float4*)yp)[lane * 2];
    float4 v1 = ((const float4*)yp)[lane * 2 + 1];
    float sum = v0.x + v0.y + v0.z + v0.w + v1.x + v1.y + v1.z + v1.w;
    float sq = v0.x * v0.x + v0.y * v0.y + v0.z * v0.z + v0.w * v0.w +
               v1.x * v1.x + v1.y * v1.y + v1.z * v1.z + v1.w * v1.w;
#pragma unroll
    for (int o = 16; o; o >>= 1) {
        sum += __shfl_xor_sync(0xffffffffu, sum, o);
        sq += __shfl_xor_sync(0xffffffffu, sq, o);
    }
    float mean = sum * (1.f / DH);
    float var = sq * (1.f / DH) - mean * mean;
    float rs = rsqrtf(var + 1e-6f);
    int dbase = h * DH + lane * 8;
    float4 sc0 = ((const float4*)(gsc + dbase))[0];
    float4 sc1 = ((const float4*)(gsc + dbase))[1];
    float4 bi0 = ((const float4*)(gbi + dbase))[0];
    float4 bi1 = ((const float4*)(gbi + dbase))[1];
    float* op = out + (size_t)(b * SS + s) * DD + dbase;
    float4 o0, o1;
    o0.x = (v0.x - mean) * rs * sc0.x + bi0.x;
    o0.y = (v0.y - mean) * rs * sc0.y + bi0.y;
    o0.z = (v0.z - mean) * rs * sc0.z + bi0.z;
    o0.w = (v0.w - mean) * rs * sc0.w + bi0.w;
    o1.x = (v1.x - mean) * rs * sc1.x + bi1.x;
    o1.y = (v1.y - mean) * rs * sc1.y + bi1.y;
    o1.z = (v1.z - mean) * rs * sc1.z + bi1.z;
    o1.w = (v1.w - mean) * rs * sc1.w + bi1.w;
    ((float4*)op)[0] = o0;
    ((float4*)op)[1] = o1;
}

// ---------------- launch ----------------
extern "C" void kernel_launch(void* const* d_in, const int* in_sizes, int n_in,
                              void* d_out, int out_size) {
    const float* x   = (const float*)d_in[0];
    const float* ck  = (const float*)d_in[1];
    const float* cb  = (const float*)d_in[2];
    const float* w_i = (const float*)d_in[3];
    const float* w_f = (const float*)d_in[4];
    const float* w_z = (const float*)d_in[5];
    const float* w_o = (const float*)d_in[6];
    const float* wr  = (const float*)d_in[7];
    const float* rb  = (const float*)d_in[8];
    const float* gsc = (const float*)d_in[9];
    const float* gbi = (const float*)d_in[10];
    float* out = (float*)d_out;

    conv_swish_k<<<BB * SS, 256>>>(x, ck, cb);
    dim3 gg(16, 8, 16);
    gates_gemm_k<<<gg, 256>>>(x, w_i, w_f, w_z, w_o);
    dim3 gr(NSLICE, NH);  // 4 clusters of 8 CTAs: one cluster per head
    rec_k<<<gr, 256>>>(wr, rb);
    gnorm_k<<<BB * SS, 128>>>(gsc, gbi, out);
}